// round 9
// baseline (speedup 1.0000x reference)
#include <cuda_runtime.h>
#include <cuda_bf16.h>
#include <cstdint>

#define DD 128
#define MAX_N 100000
#define MAX_E 1600000
#define TILE_R 64
#define WS_STRIDE 132   // W tile row stride (floats), float4-aligned
#define AS_STRIDE 132   // A tile row stride (floats), float4-aligned

// Scratch (device globals — no allocation allowed)
__device__ float g_h[(size_t)MAX_N * DD];
__device__ float g_h2[(size_t)MAX_N * DD];
__device__ int   g_degi[MAX_N];
__device__ int   g_off[MAX_N + 1];
__device__ int   g_cursor[MAX_N];
__device__ int   g_bsum[1024];
__device__ int   g_csr[MAX_E];

// ---------------------------------------------------------------------------
// h[n][:] = emb[annotation[n]][:]  (warp per node) ; also zeroes degi
__global__ void embed_kernel(const int* __restrict__ ann,
                             const float4* __restrict__ emb,
                             float4* __restrict__ h,
                             int* __restrict__ degi, int N) {
    int gid = blockIdx.x * blockDim.x + threadIdx.x;
    if (gid < N) degi[gid] = 0;
    int n = gid >> 5;
    int lane = gid & 31;
    if (n >= N) return;
    int a = __ldg(ann + n);
    h[(size_t)n * 32 + lane] = __ldg(emb + (size_t)a * 32 + lane);
}

__global__ void degi_kernel(const int* __restrict__ dst, int* __restrict__ degi, int E) {
    int e = blockIdx.x * blockDim.x + threadIdx.x;
    if (e < E) atomicAdd(degi + dst[e], 1);
}

// Block-local exclusive scan (Hillis-Steele in smem), emits block sums
__global__ void scan1_kernel(const int* __restrict__ degi, int* __restrict__ off,
                             int* __restrict__ bsum, int N) {
    __shared__ int s[256];
    int t = threadIdx.x;
    int i = blockIdx.x * 256 + t;
    int v = (i < N) ? degi[i] : 0;
    s[t] = v;
    __syncthreads();
#pragma unroll
    for (int d = 1; d < 256; d <<= 1) {
        int add = (t >= d) ? s[t - d] : 0;
        __syncthreads();
        s[t] += add;
        __syncthreads();
    }
    if (i < N) off[i] = s[t] - v;            // exclusive within block
    if (t == 255) bsum[blockIdx.x] = s[255]; // block total
}

// Per-block: prefix = sum(bsum[0..b)), finalize off and cursor in one pass
__global__ void scan23_kernel(int* __restrict__ off, int* __restrict__ cursor,
                              const int* __restrict__ bsum, int N, int E) {
    __shared__ int s[256];
    int t = threadIdx.x;
    int b = blockIdx.x;
    int acc = 0;
    for (int j = t; j < b; j += 256) acc += bsum[j];
    s[t] = acc;
    __syncthreads();
#pragma unroll
    for (int d = 128; d > 0; d >>= 1) {
        if (t < d) s[t] += s[t + d];
        __syncthreads();
    }
    int prefix = s[0];
    int i = b * 256 + t;
    if (i < N) {
        int o = off[i] + prefix;
        off[i] = o;
        cursor[i] = o;
    }
    if (i == 0) off[N] = E;
}

__global__ void place_kernel(const int* __restrict__ src, const int* __restrict__ dst,
                             int* __restrict__ cursor, int* __restrict__ csr, int E) {
    int e = blockIdx.x * blockDim.x + threadIdx.x;
    if (e >= E) return;
    int pos = atomicAdd(cursor + dst[e], 1);
    csr[pos] = src[e];
}

// ---------------------------------------------------------------------------
// Fused persistent layer: out[r] = relu( ((hin[r] + sum_nbr hin) / (deg+1)) @ W + b )
// hin and hout are DISTINCT buffers (ping-pong) -> no read/write race.
// Each block loads W once, then loops row-tiles: gather 64 rows into smem,
// then col-packed f32x2 GEMM.
__global__ __launch_bounds__(256, 2)
void fused_layer_kernel(const float4* __restrict__ hin,
                        const int* __restrict__ off,
                        const int* __restrict__ csr,
                        const float* __restrict__ W,
                        const float* __restrict__ bias,
                        float* __restrict__ hout, int N, int ntiles) {
    extern __shared__ float sh[];
    float* Wsh = sh;                        // DD x WS_STRIDE, row-major [k][c]
    float* Ash = sh + DD * WS_STRIDE;       // TILE_R x AS_STRIDE

    int tx = threadIdx.x & 31;              // lane
    int wid = threadIdx.x >> 5;             // warp 0..7
    int tid = threadIdx.x;

    // ---- Load W once (row-major, stride WS_STRIDE) ----
    {
        const float4* Wg = (const float4*)W;
#pragma unroll
        for (int j = 0; j < (DD * DD / 4) / 256; j++) {
            int idx = tid + j * 256;        // = k*32 + c4
            int k  = idx >> 5;
            int c4 = idx & 31;
            *(float4*)&Wsh[k * WS_STRIDE + c4 * 4] = __ldg(Wg + idx);
        }
    }
    float4 b4 = __ldg((const float4*)bias + tx);

    int ty = wid;                           // 0..7, GEMM row group

    for (int tile = blockIdx.x; tile < ntiles; tile += gridDim.x) {
        int r0 = tile * TILE_R;

        // ---- Phase 1: gather 64 rows into Ash (warp per node, 8 rounds) ----
#pragma unroll 1
        for (int rr = 0; rr < 8; rr++) {
            int row = rr * 8 + wid;         // 0..63
            int n = r0 + row;
            if (n < N) {
                int beg = __ldg(off + n);
                int end = __ldg(off + n + 1);
                float4 acc = __ldg(hin + (size_t)n * 32 + tx);   // self
                int i = beg;
                for (; i + 4 <= end; i += 4) {
                    int s0 = __ldg(csr + i);
                    int s1 = __ldg(csr + i + 1);
                    int s2 = __ldg(csr + i + 2);
                    int s3 = __ldg(csr + i + 3);
                    float4 v0 = __ldg(hin + (size_t)s0 * 32 + tx);
                    float4 v1 = __ldg(hin + (size_t)s1 * 32 + tx);
                    float4 v2 = __ldg(hin + (size_t)s2 * 32 + tx);
                    float4 v3 = __ldg(hin + (size_t)s3 * 32 + tx);
                    acc.x += v0.x + v1.x + v2.x + v3.x;
                    acc.y += v0.y + v1.y + v2.y + v3.y;
                    acc.z += v0.z + v1.z + v2.z + v3.z;
                    acc.w += v0.w + v1.w + v2.w + v3.w;
                }
                for (; i < end; i++) {
                    int s = __ldg(csr + i);
                    float4 v = __ldg(hin + (size_t)s * 32 + tx);
                    acc.x += v.x; acc.y += v.y; acc.z += v.z; acc.w += v.w;
                }
                *(float4*)&Ash[row * AS_STRIDE + tx * 4] = acc;
            } else {
                *(float4*)&Ash[row * AS_STRIDE + tx * 4] =
                    make_float4(0.f, 0.f, 0.f, 0.f);
            }
        }
        __syncthreads();

        // ---- Phase 2: GEMM (col-packed f32x2; thread = rows ty+8i, cols 4tx..4tx+3) ----
        unsigned long long acc2[8][2];
#pragma unroll
        for (int i = 0; i < 8; i++) { acc2[i][0] = 0ULL; acc2[i][1] = 0ULL; }

#pragma unroll 8
        for (int k = 0; k < DD; k++) {
            float4 wv = *(const float4*)&Wsh[k * WS_STRIDE + tx * 4];
            unsigned long long w2a, w2b;
            asm("mov.b64 %0, {%1,%2};" : "=l"(w2a) : "f"(wv.x), "f"(wv.y));
            asm("mov.b64 %0, {%1,%2};" : "=l"(w2b) : "f"(wv.z), "f"(wv.w));
#pragma unroll
            for (int i = 0; i < 8; i++) {
                float a = Ash[(i * 8 + ty) * AS_STRIDE + k];
                unsigned long long a2;
                asm("mov.b64 %0, {%1,%1};" : "=l"(a2) : "f"(a));
                asm("fma.rn.f32x2 %0, %1, %2, %0;" : "+l"(acc2[i][0]) : "l"(a2), "l"(w2a));
                asm("fma.rn.f32x2 %0, %1, %2, %0;" : "+l"(acc2[i][1]) : "l"(a2), "l"(w2b));
            }
        }

#pragma unroll
        for (int i = 0; i < 8; i++) {
            int row = r0 + i * 8 + ty;
            if (row < N) {
                int deg = __ldg(off + row + 1) - __ldg(off + row);
                float invr = 1.0f / (float)(deg + 1);
                unsigned int l0, h0, l1, h1;
                asm("mov.b64 {%0,%1}, %2;" : "=r"(l0), "=r"(h0) : "l"(acc2[i][0]));
                asm("mov.b64 {%0,%1}, %2;" : "=r"(l1), "=r"(h1) : "l"(acc2[i][1]));
                float4 o;
                o.x = fmaxf(__uint_as_float(l0) * invr + b4.x, 0.0f);
                o.y = fmaxf(__uint_as_float(h0) * invr + b4.y, 0.0f);
                o.z = fmaxf(__uint_as_float(l1) * invr + b4.z, 0.0f);
                o.w = fmaxf(__uint_as_float(h1) * invr + b4.w, 0.0f);
                *(float4*)(hout + (size_t)row * DD + tx * 4) = o;
            }
        }
        __syncthreads();   // Ash reused next tile
    }
}

// ---------------------------------------------------------------------------
extern "C" void kernel_launch(void* const* d_in, const int* in_sizes, int n_in,
                              void* d_out, int out_size) {
    const int*   ann = (const int*)d_in[0];
    const int*   src = (const int*)d_in[1];
    const int*   dst = (const int*)d_in[2];
    const float* emb = (const float*)d_in[3];
    const float* Ws  = (const float*)d_in[4];
    const float* bs  = (const float*)d_in[5];

    int N = in_sizes[0];
    int E = in_sizes[1];
    int L = in_sizes[4] / (DD * DD);

    float *hA, *hB;
    int *degi, *off, *cursor, *bsum, *csr;
    cudaGetSymbolAddress((void**)&hA,     g_h);
    cudaGetSymbolAddress((void**)&hB,     g_h2);
    cudaGetSymbolAddress((void**)&degi,   g_degi);
    cudaGetSymbolAddress((void**)&off,    g_off);
    cudaGetSymbolAddress((void**)&cursor, g_cursor);
    cudaGetSymbolAddress((void**)&bsum,   g_bsum);
    cudaGetSymbolAddress((void**)&csr,    g_csr);
    float* out = (float*)d_out;

    int nb = (N + 255) / 256;

    // 1) h0 = emb[annotation]  (+ zero degi)
    {
        long long t = (long long)N * 32;
        embed_kernel<<<(unsigned)((t + 255) / 256), 256>>>(ann, (const float4*)emb,
                                                           (float4*)hA, degi, N);
    }
    // 2-5) CSR build
    degi_kernel<<<(E + 255) / 256, 256>>>(dst, degi, E);
    scan1_kernel<<<nb, 256>>>(degi, off, bsum, N);
    scan23_kernel<<<nb, 256>>>(off, cursor, bsum, N, E);
    place_kernel<<<(E + 255) / 256, 256>>>(src, dst, cursor, csr, E);

    size_t shbytes = (size_t)(DD * WS_STRIDE + TILE_R * AS_STRIDE) * sizeof(float);
    cudaFuncSetAttribute(fused_layer_kernel,
                         cudaFuncAttributeMaxDynamicSharedMemorySize, (int)shbytes);

    int ntiles = (N + TILE_R - 1) / TILE_R;
    int grid = 2 * 148;
    if (grid > ntiles) grid = ntiles;

    float* cur = hA;
    float* nxt = hB;
    for (int l = 0; l < L; l++) {
        float* dstbuf = (l == L - 1) ? out : nxt;
        fused_layer_kernel<<<grid, 256, shbytes>>>((const float4*)cur, off, csr,
                                                   Ws + (size_t)l * DD * DD,
                                                   bs + (size_t)l * DD,
                                                   dstbuf, N, ntiles);
        float* t = cur; cur = nxt; nxt = t;
    }
}